// round 4
// baseline (speedup 1.0000x reference)
#include <cuda_runtime.h>
#include <math.h>

#define IMG    256
#define PSZ    16
#define PAD    8
#define WX     28      // aligned x-window
#define WY     24      // y-window
#define NBR    64
#define CH     3
#define INV2S2 12.5f
#define EPSV   1e-7f
#define PADP   20      // patchT row pitch [c][q][p]
#define PFX    28      // FxT row pitch   [q][wl]  (exact, no pad)
#define PFY    24      // FyT row pitch   [p][hl]  (exact, no pad)
#define PT     28      // tT row pitch    [c][p][wl]
#define NBRUSH 2048

// scratch: precomputed filters + window origins
__device__ float fx_g[NBRUSH * PSZ * PFX];   // [bn][q][wl], includes 1/N
__device__ float fy_g[NBRUSH * PSZ * PFY];   // [bn][p][hl]
__device__ int   wx0_g[NBRUSH];
__device__ int   wy0_g[NBRUSH];

// ---- prep: zero output slice + build filters for 4 brushes per CTA ----
__global__ __launch_bounds__(256) void prep_kernel(
    const float* __restrict__ brushes, float4* __restrict__ outz, int n4)
{
    const int cta = blockIdx.x;
    const int tid = threadIdx.x;

    // part 1: zero a 3072-float4 slice
    {
        const int base = cta * 3072;
        #pragma unroll
        for (int i = 0; i < 12; i++) {
            const int idx = base + tid + i * 256;
            if (idx < n4) outz[idx] = make_float4(0.f, 0.f, 0.f, 0.f);
        }
    }

    // part 2: filters for brushes bn0..bn0+3
    const int bn0 = cta * 4;
    __shared__ float g_s[4][2];
    __shared__ float den_s[4][32];   // [slot][ax*16+q]

    if (tid < 8) {
        const int slot = tid >> 1;
        const int ax   = tid & 1;
        const float gv = brushes[(bn0 + slot) * 2 + ax] * (float)IMG;
        g_s[slot][ax] = gv;
        const int base = (int)floorf(gv) - 11;
        if (ax == 0) wx0_g[bn0 + slot] = base & ~3;
        else         wy0_g[bn0 + slot] = base;
    }
    __syncthreads();

    if (tid < 128) {
        const int slot = tid >> 5;
        const int r    = tid & 31;
        const int ax   = r >> 4;
        const int q    = r & 15;
        const float mu = g_s[slot][ax] + (float)q - 7.5f;
        const int i0 = (int)floorf(mu) - 4;
        float s = 0.f;
        #pragma unroll
        for (int k = 0; k < 10; k++) {
            const int i = i0 + k;
            if (i >= -PAD && i <= IMG + PAD - 1) {
                const float d = (float)i - mu;
                s += __expf(-d * d * INV2S2);
            }
        }
        den_s[slot][r] = s + EPSV;
    }
    __syncthreads();

    // fx: 4 * 448 values
    for (int i = tid; i < 4 * PSZ * PFX; i += 256) {
        const int slot = i / (PSZ * PFX);
        const int r    = i - slot * (PSZ * PFX);
        const int q    = r / PFX;
        const int wl   = r - q * PFX;
        const int w    = wx0_g[bn0 + slot] + wl;   // just written by this CTA? no — use recompute
        float val = 0.f;
        const float gv = g_s[slot][0];
        const int w0 = (((int)floorf(gv)) - 11) & ~3;
        const int ww = w0 + wl;
        if (ww >= 0 && ww < IMG) {
            const float mu = gv + (float)q - 7.5f;
            const float d  = (float)ww - mu;
            val = __expf(-d * d * INV2S2) / den_s[slot][q] * (1.0f / (float)NBR);
        }
        (void)w;
        fx_g[(size_t)(bn0 + slot) * (PSZ * PFX) + r] = val;
    }
    // fy: 4 * 384 values
    for (int i = tid; i < 4 * PSZ * PFY; i += 256) {
        const int slot = i / (PSZ * PFY);
        const int r    = i - slot * (PSZ * PFY);
        const int p    = r / PFY;
        const int hl   = r - p * PFY;
        const float gv = g_s[slot][1];
        const int h0 = ((int)floorf(gv)) - 11;
        const int h  = h0 + hl;
        float val = 0.f;
        if (h >= 0 && h < IMG) {
            const float mu = gv + (float)p - 7.5f;
            const float d  = (float)h - mu;
            val = __expf(-d * d * INV2S2) / den_s[slot][PSZ + p];
        }
        fy_g[(size_t)(bn0 + slot) * (PSZ * PFY) + r] = val;
    }
}

// ---- scatter: 2 brushes per CTA, filters preloaded from scratch ----
__global__ __launch_bounds__(256, 5) void brush_scatter_kernel(
    const float* __restrict__ patches,   // [B, N, 3, 16, 16]
    float* __restrict__ out)             // [B, 3, 256, 256]
{
    __shared__ __align__(16) float patchT_s[2][CH * PSZ * PADP];
    __shared__ __align__(16) float FxT_s[2][PSZ * PFX];
    __shared__ __align__(16) float FyT_s[2][PSZ * PFY];
    __shared__ __align__(16) float tT_s[2][CH * PSZ * PT];
    __shared__ int w0_s[2][2];

    const int bn0 = blockIdx.x * 2;
    const int b   = bn0 >> 6;
    const int tid = threadIdx.x;

    if (tid < 4) {
        const int slot = tid >> 1;
        w0_s[slot][tid & 1] = (tid & 1) ? wy0_g[bn0 + slot] : wx0_g[bn0 + slot];
    }

    // filters: linear float4 copies (fx 2*448, fy 2*384 floats)
    {
        const float4* fx4 = (const float4*)(fx_g + (size_t)bn0 * (PSZ * PFX));
        float4* dfx = (float4*)&FxT_s[0][0];
        #pragma unroll
        for (int i = tid; i < 224; i += 256) dfx[i] = fx4[i];
        const float4* fy4 = (const float4*)(fy_g + (size_t)bn0 * (PSZ * PFY));
        float4* dfy = (float4*)&FyT_s[0][0];
        if (tid < 192) dfy[tid] = fy4[tid];
    }

    // patch transpose loads: 1536 elems, 6 per thread
    {
        const float* pbase = patches + (size_t)bn0 * (CH * PSZ * PSZ);
        #pragma unroll
        for (int it = 0; it < 6; it++) {
            const int i = tid + it * 256;
            const int slot = i >= 768;
            const int r = i - slot * 768;
            const int c = r >> 8;
            const int p = (r >> 4) & 15;
            const int q = r & 15;
            patchT_s[slot][(c * PSZ + q) * PADP + p] = pbase[i];
        }
    }
    __syncthreads();

    // stage 1: tT[c][p][wl] = sum_q FxT[q][wl] * patchT[c][q][p]
    if (tid < 168) {
        const int wlq = tid % 7;
        int u = tid / 7;
        const int pg = u & 3;  u >>= 2;
        const int c  = u % 3;
        const int slot = u / 3;
        const int p0  = pg * 4;
        const int wl0 = wlq * 4;

        float acc[4][4] = {};
        #pragma unroll
        for (int q = 0; q < PSZ; q++) {
            const float4 fx = *(const float4*)&FxT_s[slot][q * PFX + wl0];
            const float4 pv = *(const float4*)&patchT_s[slot][(c * PSZ + q) * PADP + p0];
            const float fxa[4] = {fx.x, fx.y, fx.z, fx.w};
            const float pva[4] = {pv.x, pv.y, pv.z, pv.w};
            #pragma unroll
            for (int i = 0; i < 4; i++)
                #pragma unroll
                for (int pp = 0; pp < 4; pp++)
                    acc[i][pp] = fmaf(fxa[i], pva[pp], acc[i][pp]);
        }
        #pragma unroll
        for (int pp = 0; pp < 4; pp++) {
            float4 o = make_float4(acc[0][pp], acc[1][pp], acc[2][pp], acc[3][pp]);
            *(float4*)&tT_s[slot][(c * PSZ + p0 + pp) * PT + wl0] = o;
        }
    }
    __syncthreads();

    // stage 2: 4x4 output blocks, vectorized global reduction
    if (tid < 252) {
        const int wlq = tid % 7;
        int u = tid / 7;
        const int hlg = u % 6;  u /= 6;
        const int c   = u % 3;
        const int slot = u / 3;
        const int wl0 = wlq * 4;
        const int hl0 = hlg * 4;

        float acc[4][4] = {};
        #pragma unroll
        for (int p = 0; p < PSZ; p++) {
            const float4 tv = *(const float4*)&tT_s[slot][(c * PSZ + p) * PT + wl0];
            const float4 fy = *(const float4*)&FyT_s[slot][p * PFY + hl0];
            const float fya[4] = {fy.x, fy.y, fy.z, fy.w};
            const float tva[4] = {tv.x, tv.y, tv.z, tv.w};
            #pragma unroll
            for (int i = 0; i < 4; i++)
                #pragma unroll
                for (int k = 0; k < 4; k++)
                    acc[i][k] = fmaf(fya[i], tva[k], acc[i][k]);
        }

        const int wb = w0_s[slot][0] + wl0;
        const int hb = w0_s[slot][1] + hl0;
        float* base = out + ((size_t)b * CH + c) * (IMG * IMG);
        const bool wok = (wb >= 0) && (wb + 3 < IMG);
        #pragma unroll
        for (int i = 0; i < 4; i++) {
            const int h = hb + i;
            if (h < 0 || h >= IMG) continue;
            float* row = base + (size_t)h * IMG;
            if (wok) {
                asm volatile("red.global.add.v4.f32 [%0], {%1, %2, %3, %4};"
                             :: "l"(row + wb), "f"(acc[i][0]), "f"(acc[i][1]),
                                "f"(acc[i][2]), "f"(acc[i][3])
                             : "memory");
            } else {
                #pragma unroll
                for (int k = 0; k < 4; k++) {
                    const int w = wb + k;
                    if (w >= 0 && w < IMG) atomicAdd(row + w, acc[i][k]);
                }
            }
        }
    }
}

extern "C" void kernel_launch(void* const* d_in, const int* in_sizes, int n_in,
                              void* d_out, int out_size) {
    const float* brushes = (const float*)d_in[0];   // [32,64,2]
    const float* patches = (const float*)d_in[1];   // [32,64,3,16,16]
    float* out = (float*)d_out;                     // [32,3,256,256]

    const int n4 = out_size / 4;
    prep_kernel<<<512, 256>>>(brushes, (float4*)out, n4);
    brush_scatter_kernel<<<NBRUSH / 2, 256>>>(patches, out);
}

// round 5
// speedup vs baseline: 1.2567x; 1.2567x over previous
#include <cuda_runtime.h>
#include <math.h>

#define IMG    256
#define PSZ    16
#define PAD    8
#define WX     28      // aligned x-window
#define WY     24      // y-window
#define NBR    64
#define CH     3
#define INV2S2 12.5f
#define EPSV   1e-7f
#define PADP   20      // patchT row pitch [c][q][p]
#define PFX    28      // FxT row pitch   [q][wl]
#define PFY    24      // FyT row pitch   [p][hl]
#define PT     28      // tT row pitch    [c][p][wl]
#define NBRUSH 2048

// scratch: precomputed filters + window origins
__device__ float fx_g[NBRUSH * PSZ * PFX];   // [bn][q][wl], includes 1/N
__device__ float fy_g[NBRUSH * PSZ * PFY];   // [bn][p][hl]
__device__ int   wx0_g[NBRUSH];
__device__ int   wy0_g[NBRUSH];

// ---- prep: zero output slice + table-based filters for 4 brushes per CTA ----
__global__ __launch_bounds__(256) void prep_kernel(
    const float* __restrict__ brushes, float4* __restrict__ outz, int n4)
{
    const int cta = blockIdx.x;
    const int tid = threadIdx.x;
    const int bn0 = cta * 4;

    __shared__ float e_s[4][2][8];      // exp table per (slot, axis)
    __shared__ float rden_s[4][2][16];  // reciprocal denominators (x incl 1/64)
    __shared__ int   t0_s[4][2];
    __shared__ int   w0_s[4][2];

    // part 1: zero a 3072-float4 slice of the output
    {
        const int base = cta * 3072;
        #pragma unroll
        for (int i = 0; i < 12; i++) {
            const int idx = base + tid + i * 256;
            if (idx < n4) outz[idx] = make_float4(0.f, 0.f, 0.f, 0.f);
        }
    }

    // part 2a: brush params
    if (tid < 8) {
        const int slot = tid >> 1;
        const int ax   = tid & 1;
        const float g  = brushes[(bn0 + slot) * 2 + ax] * (float)IMG;
        const int fl   = (int)floorf(g);
        t0_s[slot][ax] = fl - 10;
        const int w0   = (ax == 0) ? ((fl - 11) & ~3) : (fl - 11);
        w0_s[slot][ax] = w0;
        if (ax == 0) wx0_g[bn0 + slot] = w0;
        else         wy0_g[bn0 + slot] = w0;
    }

    // part 2b: 8-entry exp tables + denominators (threads 32..95, whole warps)
    if (tid >= 32 && tid < 96) {
        const int t    = tid - 32;
        const int slot = t >> 4;
        const int ax   = (t >> 3) & 1;
        const int k    = t & 7;
        const float g  = brushes[(bn0 + slot) * 2 + ax] * (float)IMG;
        const int  t0  = (int)floorf(g) - 10;
        const float d  = (float)(t0 + k) - (g - 7.5f);
        e_s[slot][ax][k] = __expf(-d * d * INV2S2);
        __syncwarp();
        // denominators: each thread handles q = k and q = k+8
        #pragma unroll
        for (int h = 0; h < 2; h++) {
            const int q = k + h * 8;
            int klo = -PAD - q - t0;         if (klo < 0) klo = 0;
            int khi = (IMG + PAD - 1) - q - t0; if (khi > 7) khi = 7;
            float s = 0.f;
            #pragma unroll
            for (int kk = 0; kk < 8; kk++)
                if (kk >= klo && kk <= khi) s += e_s[slot][ax][kk];
            s += EPSV;
            rden_s[slot][ax][q] = (ax == 0) ? 1.f / (s * (float)NBR) : 1.f / s;
        }
    }
    __syncthreads();

    // part 2c: fill filter tables via lookups (4 * (448 + 384) = 3328 values)
    for (int i = tid; i < 4 * 832; i += 256) {
        const int slot = i / 832;
        const int r    = i - slot * 832;
        if (r < PSZ * PFX) {
            const int q  = r / PFX;
            const int wl = r - q * PFX;
            const int w  = w0_s[slot][0] + wl;
            const int idx = w - q - t0_s[slot][0];
            float val = 0.f;
            if (w >= 0 && w < IMG && idx >= 0 && idx < 8)
                val = e_s[slot][0][idx] * rden_s[slot][0][q];
            fx_g[(size_t)(bn0 + slot) * (PSZ * PFX) + r] = val;
        } else {
            const int rr = r - PSZ * PFX;
            const int p  = rr / PFY;
            const int hl = rr - p * PFY;
            const int h  = w0_s[slot][1] + hl;
            const int idx = h - p - t0_s[slot][1];
            float val = 0.f;
            if (h >= 0 && h < IMG && idx >= 0 && idx < 8)
                val = e_s[slot][1][idx] * rden_s[slot][1][p];
            fy_g[(size_t)(bn0 + slot) * (PSZ * PFY) + rr] = val;
        }
    }
}

// ---- scatter: 2 brushes per CTA, filters preloaded from scratch (R4, 14.9us) ----
__global__ __launch_bounds__(256, 5) void brush_scatter_kernel(
    const float* __restrict__ patches,   // [B, N, 3, 16, 16]
    float* __restrict__ out)             // [B, 3, 256, 256]
{
    __shared__ __align__(16) float patchT_s[2][CH * PSZ * PADP];
    __shared__ __align__(16) float FxT_s[2][PSZ * PFX];
    __shared__ __align__(16) float FyT_s[2][PSZ * PFY];
    __shared__ __align__(16) float tT_s[2][CH * PSZ * PT];
    __shared__ int w0_s[2][2];

    const int bn0 = blockIdx.x * 2;
    const int b   = bn0 >> 6;
    const int tid = threadIdx.x;

    if (tid < 4) {
        const int slot = tid >> 1;
        w0_s[slot][tid & 1] = (tid & 1) ? wy0_g[bn0 + slot] : wx0_g[bn0 + slot];
    }

    // filters: linear float4 copies
    {
        const float4* fx4 = (const float4*)(fx_g + (size_t)bn0 * (PSZ * PFX));
        float4* dfx = (float4*)&FxT_s[0][0];
        if (tid < 224) dfx[tid] = fx4[tid];
        const float4* fy4 = (const float4*)(fy_g + (size_t)bn0 * (PSZ * PFY));
        float4* dfy = (float4*)&FyT_s[0][0];
        if (tid < 192) dfy[tid] = fy4[tid];
    }

    // patch transpose loads: 1536 elems, 6 per thread
    {
        const float* pbase = patches + (size_t)bn0 * (CH * PSZ * PSZ);
        #pragma unroll
        for (int it = 0; it < 6; it++) {
            const int i = tid + it * 256;
            const int slot = i >= 768;
            const int r = i - slot * 768;
            const int c = r >> 8;
            const int p = (r >> 4) & 15;
            const int q = r & 15;
            patchT_s[slot][(c * PSZ + q) * PADP + p] = pbase[i];
        }
    }
    __syncthreads();

    // stage 1: tT[c][p][wl] = sum_q FxT[q][wl] * patchT[c][q][p]
    if (tid < 168) {
        const int wlq = tid % 7;
        int u = tid / 7;
        const int pg = u & 3;  u >>= 2;
        const int c  = u % 3;
        const int slot = u / 3;
        const int p0  = pg * 4;
        const int wl0 = wlq * 4;

        float acc[4][4] = {};
        #pragma unroll
        for (int q = 0; q < PSZ; q++) {
            const float4 fx = *(const float4*)&FxT_s[slot][q * PFX + wl0];
            const float4 pv = *(const float4*)&patchT_s[slot][(c * PSZ + q) * PADP + p0];
            const float fxa[4] = {fx.x, fx.y, fx.z, fx.w};
            const float pva[4] = {pv.x, pv.y, pv.z, pv.w};
            #pragma unroll
            for (int i = 0; i < 4; i++)
                #pragma unroll
                for (int pp = 0; pp < 4; pp++)
                    acc[i][pp] = fmaf(fxa[i], pva[pp], acc[i][pp]);
        }
        #pragma unroll
        for (int pp = 0; pp < 4; pp++) {
            float4 o = make_float4(acc[0][pp], acc[1][pp], acc[2][pp], acc[3][pp]);
            *(float4*)&tT_s[slot][(c * PSZ + p0 + pp) * PT + wl0] = o;
        }
    }
    __syncthreads();

    // stage 2: 4x4 output blocks, vectorized global reduction
    if (tid < 252) {
        const int wlq = tid % 7;
        int u = tid / 7;
        const int hlg = u % 6;  u /= 6;
        const int c   = u % 3;
        const int slot = u / 3;
        const int wl0 = wlq * 4;
        const int hl0 = hlg * 4;

        float acc[4][4] = {};
        #pragma unroll
        for (int p = 0; p < PSZ; p++) {
            const float4 tv = *(const float4*)&tT_s[slot][(c * PSZ + p) * PT + wl0];
            const float4 fy = *(const float4*)&FyT_s[slot][p * PFY + hl0];
            const float fya[4] = {fy.x, fy.y, fy.z, fy.w};
            const float tva[4] = {tv.x, tv.y, tv.z, tv.w};
            #pragma unroll
            for (int i = 0; i < 4; i++)
                #pragma unroll
                for (int k = 0; k < 4; k++)
                    acc[i][k] = fmaf(fya[i], tva[k], acc[i][k]);
        }

        const int wb = w0_s[slot][0] + wl0;
        const int hb = w0_s[slot][1] + hl0;
        float* base = out + ((size_t)b * CH + c) * (IMG * IMG);
        const bool wok = (wb >= 0) && (wb + 3 < IMG);
        #pragma unroll
        for (int i = 0; i < 4; i++) {
            const int h = hb + i;
            if (h < 0 || h >= IMG) continue;
            float* row = base + (size_t)h * IMG;
            if (wok) {
                asm volatile("red.global.add.v4.f32 [%0], {%1, %2, %3, %4};"
                             :: "l"(row + wb), "f"(acc[i][0]), "f"(acc[i][1]),
                                "f"(acc[i][2]), "f"(acc[i][3])
                             : "memory");
            } else {
                #pragma unroll
                for (int k = 0; k < 4; k++) {
                    const int w = wb + k;
                    if (w >= 0 && w < IMG) atomicAdd(row + w, acc[i][k]);
                }
            }
        }
    }
}

extern "C" void kernel_launch(void* const* d_in, const int* in_sizes, int n_in,
                              void* d_out, int out_size) {
    const float* brushes = (const float*)d_in[0];   // [32,64,2]
    const float* patches = (const float*)d_in[1];   // [32,64,3,16,16]
    float* out = (float*)d_out;                     // [32,3,256,256]

    const int n4 = out_size / 4;
    prep_kernel<<<512, 256>>>(brushes, (float4*)out, n4);
    brush_scatter_kernel<<<NBRUSH / 2, 256>>>(patches, out);
}